// round 9
// baseline (speedup 1.0000x reference)
#include <cuda_runtime.h>
#include <cuda_bf16.h>
#include <cstdint>
#include <math.h>

#define LSEQ     2048
#define HIDDEN   2048
#define INTER    4096
#define HEADS    64
#define HEAD_DIM 64
#define STATE    64
#define KCONV    4
#define CONV_DIM (INTER + 2 * STATE)            // 4224
#define PROJ     (INTER + CONV_DIM + HEADS)     // 8384
#define W1_RPAD  8448                           // PROJ padded to 128
#define QCH      64                             // chunk length
#define NC       (LSEQ / QCH)                   // 32 chunks

// ---------------- scratch ------------------------------------------------
__device__ float g_proj[(size_t)LSEQ * PROJ];
__device__ float g_conv[(size_t)LSEQ * CONV_DIM];
__device__ float g_y[(size_t)LSEQ * INTER];
__device__ float g_dtv[LSEQ * HEADS];
__device__ float g_dA[LSEQ * HEADS];
// chunked-SSD scratch
__device__ float g_L[(size_t)HEADS * NC * QCH];        // log-decay cumsum
__device__ float g_G[(size_t)NC * QCH * QCH];          // C_i . B_tau (shared over heads)
__device__ float g_U[(size_t)HEADS * NC * 4096];       // per-chunk state increment [p][n]
__device__ float g_Sst[(size_t)HEADS * NC * 4096];     // state at chunk entry [p][n]
__device__ float g_afac[HEADS * NC];
// bf16 split operands (u32 = packed bf16 pair, k-permuted layout)
__device__ uint32_t g_h_hi[(size_t)LSEQ * (HIDDEN / 2)];
__device__ uint32_t g_h_lo[(size_t)LSEQ * (HIDDEN / 2)];
__device__ uint32_t g_w1_hi[(size_t)W1_RPAD * (HIDDEN / 2)];
__device__ uint32_t g_w1_lo[(size_t)W1_RPAD * (HIDDEN / 2)];
__device__ uint32_t g_w2_hi[(size_t)HIDDEN * (INTER / 2)];
__device__ uint32_t g_w2_lo[(size_t)HIDDEN * (INTER / 2)];
__device__ uint32_t g_yn_hi[(size_t)LSEQ * (INTER / 2)];
__device__ uint32_t g_yn_lo[(size_t)LSEQ * (INTER / 2)];

// ---------------- helpers --------------------------------------------------
__device__ __forceinline__ void split_pack(float x0, float x1, uint32_t& hi, uint32_t& lo) {
    __nv_bfloat16 h0 = __float2bfloat16(x0);
    __nv_bfloat16 h1 = __float2bfloat16(x1);
    __nv_bfloat16 l0 = __float2bfloat16(x0 - __bfloat162float(h0));
    __nv_bfloat16 l1 = __float2bfloat16(x1 - __bfloat162float(h1));
    hi = (uint32_t)__bfloat16_as_ushort(h0) | ((uint32_t)__bfloat16_as_ushort(h1) << 16);
    lo = (uint32_t)__bfloat16_as_ushort(l0) | ((uint32_t)__bfloat16_as_ushort(l1) << 16);
}

__device__ __forceinline__ void mma_bf16(float* d, const uint32_t* a, const uint32_t* b) {
    asm volatile(
        "mma.sync.aligned.m16n8k16.row.col.f32.bf16.bf16.f32 "
        "{%0,%1,%2,%3}, {%4,%5,%6,%7}, {%8,%9}, {%0,%1,%2,%3};"
        : "+f"(d[0]), "+f"(d[1]), "+f"(d[2]), "+f"(d[3])
        : "r"(a[0]), "r"(a[1]), "r"(a[2]), "r"(a[3]), "r"(b[0]), "r"(b[1]));
}

__device__ __forceinline__ uint32_t smem_u32p(const void* p) {
    uint32_t a;
    asm("{ .reg .u64 t; cvta.to.shared.u64 t, %1; cvt.u32.u64 %0, t; }" : "=r"(a) : "l"(p));
    return a;
}
__device__ __forceinline__ void cp16(uint32_t dst, const void* src) {
    asm volatile("cp.async.cg.shared.global [%0], [%1], 16;" :: "r"(dst), "l"(src));
}
__device__ __forceinline__ void cp_commit() { asm volatile("cp.async.commit_group;"); }
__device__ __forceinline__ void cp_wait1()  { asm volatile("cp.async.wait_group 1;" ::: "memory"); }
__device__ __forceinline__ void cp_wait0()  { asm volatile("cp.async.wait_group 0;" ::: "memory"); }

// ---------------- convert f32 -> permuted bf16 hi/lo pairs (R5 layout) -----
__global__ void cvt_split(const float* __restrict__ in, uint32_t* __restrict__ hi,
                          uint32_t* __restrict__ lo, int R, int K)
{
    const int K2 = K >> 1;
    int jj  = blockIdx.x * blockDim.x + threadIdx.x;
    int row = blockIdx.y;
    if (jj >= K2) return;
    int g = jj >> 3, p = jj & 7;
    int jl = (g << 3) + (p >> 1) + ((p & 1) << 2);
    float a0 = 0.f, a1 = 0.f;
    if (row < R) {
        a0 = in[(size_t)row * K + 2 * jl];
        a1 = in[(size_t)row * K + 2 * jl + 1];
    }
    uint32_t h, l;
    split_pack(a0, a1, h, l);
    hi[(size_t)row * K2 + jj] = h;
    lo[(size_t)row * K2 + jj] = l;
}

// ---------------- bf16x3 GEMM (R5 structure, measured best) ----------------
#define BM 128
#define BN 128
#define BKE 32
#define BUF_U32 (BM * 16)              // 2048
#define STAGE_U32 (4 * BUF_U32)        // 8192
#define GEMM_SMEM_BYTES (3 * STAGE_U32 * 4)   // 98304

__global__ __launch_bounds__(256, 2) void gemm_bf3(
    const uint32_t* __restrict__ Ahi, const uint32_t* __restrict__ Alo,
    const uint32_t* __restrict__ Bhi, const uint32_t* __restrict__ Blo,
    float* __restrict__ C, int M, int N, int K)
{
    extern __shared__ uint32_t dsm[];
    const int K2  = K >> 1;
    const int nst = K / BKE;
    const int tid  = threadIdx.x;
    const int wid  = tid >> 5;
    const int lane = tid & 31;
    const int wm   = wid & 1;
    const int wn   = wid >> 1;
    const int m0   = blockIdx.y * BM;
    const int n0   = blockIdx.x * BN;
    const int lg   = lane >> 2;
    const int lc   = lane & 3;

    const uint32_t sbase = smem_u32p(dsm);
    const int crow = tid >> 1;
    const int cj   = (tid & 1) * 2;
    const int rsw  = (crow >> 1) & 1;

    float acc[4][4][4];
#pragma unroll
    for (int i = 0; i < 4; ++i)
#pragma unroll
        for (int j = 0; j < 4; ++j)
#pragma unroll
            for (int q = 0; q < 4; ++q) acc[i][j][q] = 0.f;

    auto issue = [&](int s) {
        const uint32_t st = sbase + ((s % 3) * STAGE_U32) * 4;
        const size_t ga = (size_t)(m0 + crow) * K2 + (size_t)s * 16;
        const size_t gb = (size_t)(n0 + crow) * K2 + (size_t)s * 16;
#pragma unroll
        for (int c = 0; c < 2; ++c) {
            const int j  = cj + (c ^ rsw);
            const int jp = j ^ (crow & 3);
            const uint32_t d = st + (crow * 16 + jp * 4) * 4;
            cp16(d,                    Ahi + ga + j * 4);
            cp16(d + BUF_U32 * 4,      Alo + ga + j * 4);
            cp16(d + 2 * BUF_U32 * 4,  Bhi + gb + j * 4);
            cp16(d + 3 * BUF_U32 * 4,  Blo + gb + j * 4);
        }
    };

    issue(0); cp_commit();
    issue(1); cp_commit();

    for (int s = 0; s < nst; ++s) {
        if (s < nst - 1) cp_wait1(); else cp_wait0();
        __syncthreads();
        if (s + 2 < nst) { issue(s + 2); cp_commit(); }

        const uint32_t* st   = dsm + (s % 3) * STAGE_U32;
        const uint32_t* pAhi = st;
        const uint32_t* pAlo = st + BUF_U32;
        const uint32_t* pBhi = st + 2 * BUF_U32;
        const uint32_t* pBlo = st + 3 * BUF_U32;

#pragma unroll
        for (int ks = 0; ks < 2; ++ks) {
            const int jw = ks * 8 + 2 * lc;
            uint2 aH0[4], aH1[4], aL0[4], aL1[4], bH[4], bL[4];
#pragma unroll
            for (int mt = 0; mt < 4; ++mt) {
                int r0 = wm * 64 + mt * 16 + lg;
                int sx = (r0 & 3) << 2;
                int o0 = r0 * 16 + (jw ^ sx);
                int o1 = (r0 + 8) * 16 + (jw ^ sx);
                aH0[mt] = *reinterpret_cast<const uint2*>(pAhi + o0);
                aH1[mt] = *reinterpret_cast<const uint2*>(pAhi + o1);
                aL0[mt] = *reinterpret_cast<const uint2*>(pAlo + o0);
                aL1[mt] = *reinterpret_cast<const uint2*>(pAlo + o1);
            }
#pragma unroll
            for (int nt = 0; nt < 4; ++nt) {
                int rb = wn * 32 + nt * 8 + lg;
                int ob = rb * 16 + (jw ^ ((rb & 3) << 2));
                bH[nt] = *reinterpret_cast<const uint2*>(pBhi + ob);
                bL[nt] = *reinterpret_cast<const uint2*>(pBlo + ob);
            }
#pragma unroll
            for (int mt = 0; mt < 4; ++mt) {
                uint32_t ah[4] = {aH0[mt].x, aH1[mt].x, aH0[mt].y, aH1[mt].y};
#pragma unroll
                for (int nt = 0; nt < 4; ++nt) {
                    uint32_t bh[2] = {bH[nt].x, bH[nt].y};
                    mma_bf16(acc[mt][nt], ah, bh);
                }
            }
#pragma unroll
            for (int mt = 0; mt < 4; ++mt) {
                uint32_t ah[4] = {aH0[mt].x, aH1[mt].x, aH0[mt].y, aH1[mt].y};
#pragma unroll
                for (int nt = 0; nt < 4; ++nt) {
                    uint32_t bl[2] = {bL[nt].x, bL[nt].y};
                    mma_bf16(acc[mt][nt], ah, bl);
                }
            }
#pragma unroll
            for (int mt = 0; mt < 4; ++mt) {
                uint32_t al[4] = {aL0[mt].x, aL1[mt].x, aL0[mt].y, aL1[mt].y};
#pragma unroll
                for (int nt = 0; nt < 4; ++nt) {
                    uint32_t bh[2] = {bH[nt].x, bH[nt].y};
                    mma_bf16(acc[mt][nt], al, bh);
                }
            }
        }
        __syncthreads();
    }

#pragma unroll
    for (int mt = 0; mt < 4; ++mt) {
        int r0 = m0 + wm * 64 + mt * 16 + lg;
#pragma unroll
        for (int nt = 0; nt < 4; ++nt) {
            int gc = n0 + wn * 32 + nt * 8 + lc * 2;
            if (gc < N) {
                *reinterpret_cast<float2*>(&C[(size_t)r0 * N + gc]) =
                    make_float2(acc[mt][nt][0], acc[mt][nt][1]);
                *reinterpret_cast<float2*>(&C[(size_t)(r0 + 8) * N + gc]) =
                    make_float2(acc[mt][nt][2], acc[mt][nt][3]);
            }
        }
    }
}

// ---------------- fused conv+silu and dt transform --------------------------
__global__ void conv_dt_kernel(const float* __restrict__ conv_w,
                               const float* __restrict__ conv_b,
                               const float* __restrict__ dt_bias,
                               const float* __restrict__ A_log)
{
    int idx = blockIdx.x * blockDim.x + threadIdx.x;
    if (idx < LSEQ * CONV_DIM) {
        int c = idx % CONV_DIM;
        int t = idx / CONV_DIM;
        const float4 w = *reinterpret_cast<const float4*>(&conv_w[c * 4]);
        const float* col = g_proj + INTER + c;
        float acc = conv_b[c];
        if (t - 3 >= 0) acc = fmaf(col[(size_t)(t - 3) * PROJ], w.x, acc);
        if (t - 2 >= 0) acc = fmaf(col[(size_t)(t - 2) * PROJ], w.y, acc);
        if (t - 1 >= 0) acc = fmaf(col[(size_t)(t - 1) * PROJ], w.z, acc);
        acc = fmaf(col[(size_t)t * PROJ], w.w, acc);
        g_conv[idx] = acc / (1.f + expf(-acc));
    } else {
        int j = idx - LSEQ * CONV_DIM;
        if (j >= LSEQ * HEADS) return;
        int h = j & (HEADS - 1);
        int t = j >> 6;
        float z = g_proj[(size_t)t * PROJ + INTER + CONV_DIM + h] + dt_bias[h];
        float d = (z > 20.f) ? z : log1pf(expf(z));
        float A = -expf(A_log[h]);
        g_dtv[j] = d;
        g_dA[j]  = expf(d * A);
    }
}

// ================== chunked-SSD scan =========================================
// L[h][c][i] = sum_{j<=i} dt[c*Q+j,h]*A_h  (inclusive log-decay within chunk)
__global__ void chunk_L_kernel(const float* __restrict__ A_log)
{
    const int h = blockIdx.x;         // 64
    const int c = threadIdx.x;        // 32
    const float A = -expf(A_log[h]);
    float L = 0.f;
    float* Lout = g_L + ((size_t)h * NC + c) * QCH;
#pragma unroll 4
    for (int i = 0; i < QCH; ++i) {
        L = fmaf(g_dtv[(c * QCH + i) * HEADS + h], A, L);
        Lout[i] = L;
    }
    g_afac[h * NC + c] = __expf(L);
}

// G[c][i][tau] = sum_n C[c,i,n] * B[c,tau,n]   (head-independent, GROUPS=1)
__global__ __launch_bounds__(256) void chunk_G_kernel()
{
    const int c = blockIdx.x;         // 32
    __shared__ float Bs[QCH][QCH], Cs_[QCH][QCH];
    const int tid = threadIdx.x;
#pragma unroll
    for (int k = 0; k < 4; ++k) {
        int idx = tid + k * 256;                // float4 index, 0..1023
        int r = idx >> 4, col = (idx & 15) * 4;
        const float* rowp = g_conv + (size_t)(c * QCH + r) * CONV_DIM + INTER;
        *reinterpret_cast<float4*>(&Bs[r][col])  = *reinterpret_cast<const float4*>(&rowp[col]);
        *reinterpret_cast<float4*>(&Cs_[r][col]) = *reinterpret_cast<const float4*>(&rowp[STATE + col]);
    }
    __syncthreads();
    const int i = tid >> 2, tb = (tid & 3) * 16;
    for (int t = tb; t < tb + 16; ++t) {
        float acc = 0.f;
#pragma unroll 8
        for (int n = 0; n < QCH; ++n) acc = fmaf(Cs_[i][n], Bs[t][n], acc);
        g_G[((size_t)c * QCH + i) * QCH + t] = acc;
    }
}

// Per (h,c): Yintra + D*x -> g_y ; U[p][n] -> g_U
__global__ __launch_bounds__(256) void chunk_intra_kernel(const float* __restrict__ Dv)
{
    const int h = blockIdx.x >> 5;    // 64
    const int c = blockIdx.x & 31;    // 32
    const int tid = threadIdx.x;
    __shared__ float Xs[QCH][68];
    __shared__ float BG[QCH][68];
    __shared__ float Ld[QCH], dts[QCH], coef[QCH];

#pragma unroll
    for (int k = 0; k < 4; ++k) {
        int idx = tid + k * 256;
        int r = idx >> 4, col = (idx & 15) * 4;
        *reinterpret_cast<float4*>(&Xs[r][col]) = *reinterpret_cast<const float4*>(
            &g_conv[(size_t)(c * QCH + r) * CONV_DIM + h * HEAD_DIM + col]);
    }
    if (tid < QCH) {
        Ld[tid]  = g_L[((size_t)h * NC + c) * QCH + tid];
        dts[tid] = g_dtv[(c * QCH + tid) * HEADS + h];
    }
    __syncthreads();
    // decay-weighted G into BG
#pragma unroll
    for (int k = 0; k < 16; ++k) {
        int idx = tid + k * 256;
        int i = idx >> 6, t = idx & 63;
        float v = 0.f;
        if (t <= i)
            v = g_G[((size_t)c * QCH + i) * QCH + t] * __expf(Ld[i] - Ld[t]) * dts[t];
        BG[i][t] = v;
    }
    __syncthreads();
    // Yintra[i][p] = sum_t BG[i][t] * Xs[t][p];  y = Yintra + D*x
    {
        const int i = tid >> 2, p0 = (tid & 3) * 16;
        float acc[16];
#pragma unroll
        for (int u = 0; u < 16; ++u) acc[u] = 0.f;
        for (int t = 0; t < QCH; ++t) {
            float g = BG[i][t];
#pragma unroll
            for (int q = 0; q < 4; ++q) {
                float4 xv = *reinterpret_cast<const float4*>(&Xs[t][p0 + q * 4]);
                acc[q * 4 + 0] = fmaf(g, xv.x, acc[q * 4 + 0]);
                acc[q * 4 + 1] = fmaf(g, xv.y, acc[q * 4 + 1]);
                acc[q * 4 + 2] = fmaf(g, xv.z, acc[q * 4 + 2]);
                acc[q * 4 + 3] = fmaf(g, xv.w, acc[q * 4 + 3]);
            }
        }
        const float Dh = Dv[h];
        float* yp = g_y + (size_t)(c * QCH + i) * INTER + h * HEAD_DIM + p0;
#pragma unroll
        for (int q = 0; q < 4; ++q) {
            float4 o;
            o.x = acc[q * 4 + 0] + Dh * Xs[i][p0 + q * 4 + 0];
            o.y = acc[q * 4 + 1] + Dh * Xs[i][p0 + q * 4 + 1];
            o.z = acc[q * 4 + 2] + Dh * Xs[i][p0 + q * 4 + 2];
            o.w = acc[q * 4 + 3] + Dh * Xs[i][p0 + q * 4 + 3];
            *reinterpret_cast<float4*>(&yp[q * 4]) = o;
        }
    }
    __syncthreads();
    // load B into BG; coef[t] = exp(L_last - L_t)*dt_t
#pragma unroll
    for (int k = 0; k < 4; ++k) {
        int idx = tid + k * 256;
        int r = idx >> 4, col = (idx & 15) * 4;
        *reinterpret_cast<float4*>(&BG[r][col]) = *reinterpret_cast<const float4*>(
            &g_conv[(size_t)(c * QCH + r) * CONV_DIM + INTER + col]);
    }
    if (tid < QCH) coef[tid] = __expf(Ld[QCH - 1] - Ld[tid]) * dts[tid];
    __syncthreads();
    // U[p][n] = sum_t coef[t]*Xs[t][p]*BG[t][n]
    {
        const int p = tid >> 2, n0 = (tid & 3) * 16;
        float acc[16];
#pragma unroll
        for (int u = 0; u < 16; ++u) acc[u] = 0.f;
        for (int t = 0; t < QCH; ++t) {
            float xc = Xs[t][p] * coef[t];
#pragma unroll
            for (int q = 0; q < 4; ++q) {
                float4 bv = *reinterpret_cast<const float4*>(&BG[t][n0 + q * 4]);
                acc[q * 4 + 0] = fmaf(xc, bv.x, acc[q * 4 + 0]);
                acc[q * 4 + 1] = fmaf(xc, bv.y, acc[q * 4 + 1]);
                acc[q * 4 + 2] = fmaf(xc, bv.z, acc[q * 4 + 2]);
                acc[q * 4 + 3] = fmaf(xc, bv.w, acc[q * 4 + 3]);
            }
        }
        float* up = g_U + ((size_t)h * NC + c) * 4096 + p * QCH + n0;
#pragma unroll
        for (int q = 0; q < 4; ++q)
            *reinterpret_cast<float4*>(&up[q * 4]) =
                make_float4(acc[q * 4], acc[q * 4 + 1], acc[q * 4 + 2], acc[q * 4 + 3]);
    }
}

// serial over chunks: store S_in, then S = afac*S + U. grid 64h x 4 quarters.
__global__ __launch_bounds__(256) void chunk_state_kernel()
{
    const int h  = blockIdx.x >> 2;
    const int qo = (blockIdx.x & 3) * 1024;
    const int off = qo + threadIdx.x * 4;
    float4 s = make_float4(0.f, 0.f, 0.f, 0.f);
    for (int c = 0; c < NC; ++c) {
        size_t base = ((size_t)h * NC + c) * 4096 + off;
        *reinterpret_cast<float4*>(&g_Sst[base]) = s;
        float a = g_afac[h * NC + c];
        float4 u = *reinterpret_cast<const float4*>(&g_U[base]);
        s.x = fmaf(a, s.x, u.x);
        s.y = fmaf(a, s.y, u.y);
        s.z = fmaf(a, s.z, u.z);
        s.w = fmaf(a, s.w, u.w);
    }
}

// Yinter[i][p] = exp(L_i) * sum_n C[i][n]*S_in[p][n];  y += Yinter
__global__ __launch_bounds__(256) void chunk_inter_kernel()
{
    const int h = blockIdx.x >> 5;
    const int c = blockIdx.x & 31;
    const int tid = threadIdx.x;
    __shared__ float Cs_[QCH][68];
    __shared__ float ST[QCH][68];     // transposed: ST[n][p]
    __shared__ float Ld[QCH];

#pragma unroll
    for (int k = 0; k < 4; ++k) {
        int idx = tid + k * 256;
        int r = idx >> 4, col = (idx & 15) * 4;
        *reinterpret_cast<float4*>(&Cs_[r][col]) = *reinterpret_cast<const float4*>(
            &g_conv[(size_t)(c * QCH + r) * CONV_DIM + INTER + STATE + col]);
    }
    {
        const float* sp = g_Sst + ((size_t)h * NC + c) * 4096;
#pragma unroll
        for (int k = 0; k < 16; ++k) {
            int idx = tid + k * 256;          // p*64+n
            int p = idx >> 6, n = idx & 63;
            ST[n][p] = sp[idx];
        }
    }
    if (tid < QCH) Ld[tid] = g_L[((size_t)h * NC + c) * QCH + tid];
    __syncthreads();

    const int i = tid >> 2, p0 = (tid & 3) * 16;
    float acc[16];
#pragma unroll
    for (int u = 0; u < 16; ++u) acc[u] = 0.f;
    for (int n = 0; n < QCH; ++n) {
        float cv = Cs_[i][n];
#pragma unroll
        for (int q = 0; q < 4; ++q) {
            float4 sv = *reinterpret_cast<const float4*>(&ST[n][p0 + q * 4]);
            acc[q * 4 + 0] = fmaf(cv, sv.x, acc[q * 4 + 0]);
            acc[q * 4 + 1] = fmaf(cv, sv.y, acc[q * 4 + 1]);
            acc[q * 4 + 2] = fmaf(cv, sv.z, acc[q * 4 + 2]);
            acc[q * 4 + 3] = fmaf(cv, sv.w, acc[q * 4 + 3]);
        }
    }
    const float sc = __expf(Ld[i]);
    float* yp = g_y + (size_t)(c * QCH + i) * INTER + h * HEAD_DIM + p0;
#pragma unroll
    for (int q = 0; q < 4; ++q) {
        float4 o = *reinterpret_cast<float4*>(&yp[q * 4]);
        o.x += sc * acc[q * 4 + 0];
        o.y += sc * acc[q * 4 + 1];
        o.z += sc * acc[q * 4 + 2];
        o.w += sc * acc[q * 4 + 3];
        *reinterpret_cast<float4*>(&yp[q * 4]) = o;
    }
}

// ---------------- RMSNorm * silu(gate) -> bf16 hi/lo (R5 permutation) ---------
__global__ __launch_bounds__(256) void norm_gate_cvt(const float* __restrict__ nw)
{
    const int t = blockIdx.x;
    const float* y1 = g_y + (size_t)t * INTER;
    const float* gp = g_proj + (size_t)t * PROJ;
    __shared__ float red[256];
    float ss = 0.f;
    for (int c = threadIdx.x; c < INTER; c += 256) {
        float v = y1[c];
        ss = fmaf(v, v, ss);
    }
    red[threadIdx.x] = ss;
    __syncthreads();
    for (int off = 128; off > 0; off >>= 1) {
        if (threadIdx.x < off) red[threadIdx.x] += red[threadIdx.x + off];
        __syncthreads();
    }
    const float r = rsqrtf(red[0] / (float)INTER + 1e-6f);

    const int K2 = INTER / 2;
    for (int J = threadIdx.x; J < K2; J += 256) {
        int g = J >> 3, p = J & 7;
        int jl = (g << 3) + (p >> 1) + ((p & 1) << 2);
        int c0 = 2 * jl;
        float ga = gp[c0], gb = gp[c0 + 1];
        float v0 = y1[c0] * r * nw[c0] * (ga / (1.f + expf(-ga)));
        float v1 = y1[c0 + 1] * r * nw[c0 + 1] * (gb / (1.f + expf(-gb)));
        uint32_t h, l;
        split_pack(v0, v1, h, l);
        g_yn_hi[(size_t)t * K2 + J] = h;
        g_yn_lo[(size_t)t * K2 + J] = l;
    }
}

// ---------------- launch ------------------------------------------------------
extern "C" void kernel_launch(void* const* d_in, const int* in_sizes, int n_in,
                              void* d_out, int out_size)
{
    const float* hidden     = (const float*)d_in[0];
    const float* in_proj_w  = (const float*)d_in[1];
    const float* conv_w     = (const float*)d_in[2];
    const float* conv_b     = (const float*)d_in[3];
    const float* dt_bias    = (const float*)d_in[4];
    const float* A_log      = (const float*)d_in[5];
    const float* Dv         = (const float*)d_in[6];
    const float* norm_w     = (const float*)d_in[7];
    const float* out_proj_w = (const float*)d_in[8];
    float* out = (float*)d_out;

    float* p_proj = nullptr;
    cudaGetSymbolAddress((void**)&p_proj, g_proj);
    uint32_t *p_hhi, *p_hlo, *p_w1hi, *p_w1lo, *p_w2hi, *p_w2lo, *p_ynhi, *p_ynlo;
    cudaGetSymbolAddress((void**)&p_hhi, g_h_hi);
    cudaGetSymbolAddress((void**)&p_hlo, g_h_lo);
    cudaGetSymbolAddress((void**)&p_w1hi, g_w1_hi);
    cudaGetSymbolAddress((void**)&p_w1lo, g_w1_lo);
    cudaGetSymbolAddress((void**)&p_w2hi, g_w2_hi);
    cudaGetSymbolAddress((void**)&p_w2lo, g_w2_lo);
    cudaGetSymbolAddress((void**)&p_ynhi, g_yn_hi);
    cudaGetSymbolAddress((void**)&p_ynlo, g_yn_lo);

    cudaFuncSetAttribute(gemm_bf3, cudaFuncAttributeMaxDynamicSharedMemorySize, GEMM_SMEM_BYTES);

    cvt_split<<<dim3(HIDDEN / 2 / 256, LSEQ), 256>>>(hidden, p_hhi, p_hlo, LSEQ, HIDDEN);
    cvt_split<<<dim3(HIDDEN / 2 / 256, W1_RPAD), 256>>>(in_proj_w, p_w1hi, p_w1lo, PROJ, HIDDEN);
    cvt_split<<<dim3(INTER / 2 / 256, HIDDEN), 256>>>(out_proj_w, p_w2hi, p_w2lo, HIDDEN, INTER);

    // GEMM1: proj = hidden @ in_proj_w^T : M=2048, N=8384 (pad 8448), K=2048
    gemm_bf3<<<dim3(W1_RPAD / BN, LSEQ / BM), 256, GEMM_SMEM_BYTES>>>(
        p_hhi, p_hlo, p_w1hi, p_w1lo, p_proj, LSEQ, PROJ, HIDDEN);

    {
        int total = LSEQ * (CONV_DIM + HEADS);
        conv_dt_kernel<<<(total + 255) / 256, 256>>>(conv_w, conv_b, dt_bias, A_log);
    }

    // chunked-SSD scan
    chunk_L_kernel<<<HEADS, NC>>>(A_log);
    chunk_G_kernel<<<NC, 256>>>();
    chunk_intra_kernel<<<HEADS * NC, 256>>>(Dv);
    chunk_state_kernel<<<HEADS * 4, 256>>>();
    chunk_inter_kernel<<<HEADS * NC, 256>>>();

    norm_gate_cvt<<<LSEQ, 256>>>(norm_w);

    // GEMM2: out = y' @ out_proj_w^T : M=2048, N=2048, K=4096
    gemm_bf3<<<dim3(HIDDEN / BN, LSEQ / BM), 256, GEMM_SMEM_BYTES>>>(
        p_ynhi, p_ynlo, p_w2hi, p_w2lo, out, LSEQ, HIDDEN, INTER);
}

// round 10
// speedup vs baseline: 1.1332x; 1.1332x over previous
#include <cuda_runtime.h>
#include <cuda_bf16.h>
#include <cstdint>
#include <math.h>

#define LSEQ     2048
#define HIDDEN   2048
#define INTER    4096
#define HEADS    64
#define HEAD_DIM 64
#define STATE    64
#define KCONV    4
#define CONV_DIM (INTER + 2 * STATE)            // 4224
#define PROJ     (INTER + CONV_DIM + HEADS)     // 8384
#define W1_RPAD  8448                           // PROJ padded to 128

// ---------------- scratch ------------------------------------------------
__device__ float g_proj[(size_t)LSEQ * PROJ];
__device__ float g_conv[(size_t)LSEQ * CONV_DIM];
__device__ float g_y[(size_t)LSEQ * INTER];      // scan partial (n 0..31)
__device__ float g_y2[(size_t)LSEQ * INTER];     // scan partial (n 32..63)
__device__ float g_dtv[LSEQ * HEADS];
__device__ float g_dA[LSEQ * HEADS];
// bf16 split operands (u32 = packed bf16 pair, k-permuted layout)
__device__ uint32_t g_h_hi[(size_t)LSEQ * (HIDDEN / 2)];
__device__ uint32_t g_h_lo[(size_t)LSEQ * (HIDDEN / 2)];
__device__ uint32_t g_w1_hi[(size_t)W1_RPAD * (HIDDEN / 2)];
__device__ uint32_t g_w1_lo[(size_t)W1_RPAD * (HIDDEN / 2)];
__device__ uint32_t g_w2_hi[(size_t)HIDDEN * (INTER / 2)];
__device__ uint32_t g_w2_lo[(size_t)HIDDEN * (INTER / 2)];
__device__ uint32_t g_yn_hi[(size_t)LSEQ * (INTER / 2)];
__device__ uint32_t g_yn_lo[(size_t)LSEQ * (INTER / 2)];

// ---------------- helpers --------------------------------------------------
__device__ __forceinline__ void split_pack(float x0, float x1, uint32_t& hi, uint32_t& lo) {
    __nv_bfloat16 h0 = __float2bfloat16(x0);
    __nv_bfloat16 h1 = __float2bfloat16(x1);
    __nv_bfloat16 l0 = __float2bfloat16(x0 - __bfloat162float(h0));
    __nv_bfloat16 l1 = __float2bfloat16(x1 - __bfloat162float(h1));
    hi = (uint32_t)__bfloat16_as_ushort(h0) | ((uint32_t)__bfloat16_as_ushort(h1) << 16);
    lo = (uint32_t)__bfloat16_as_ushort(l0) | ((uint32_t)__bfloat16_as_ushort(l1) << 16);
}

__device__ __forceinline__ void mma_bf16(float* d, const uint32_t* a, const uint32_t* b) {
    asm volatile(
        "mma.sync.aligned.m16n8k16.row.col.f32.bf16.bf16.f32 "
        "{%0,%1,%2,%3}, {%4,%5,%6,%7}, {%8,%9}, {%0,%1,%2,%3};"
        : "+f"(d[0]), "+f"(d[1]), "+f"(d[2]), "+f"(d[3])
        : "r"(a[0]), "r"(a[1]), "r"(a[2]), "r"(a[3]), "r"(b[0]), "r"(b[1]));
}

__device__ __forceinline__ uint32_t smem_u32p(const void* p) {
    uint32_t a;
    asm("{ .reg .u64 t; cvta.to.shared.u64 t, %1; cvt.u32.u64 %0, t; }" : "=r"(a) : "l"(p));
    return a;
}
__device__ __forceinline__ void cp16(uint32_t dst, const void* src) {
    asm volatile("cp.async.cg.shared.global [%0], [%1], 16;" :: "r"(dst), "l"(src));
}
__device__ __forceinline__ void cp_commit() { asm volatile("cp.async.commit_group;"); }
__device__ __forceinline__ void cp_wait1()  { asm volatile("cp.async.wait_group 1;" ::: "memory"); }
__device__ __forceinline__ void cp_wait0()  { asm volatile("cp.async.wait_group 0;" ::: "memory"); }

// ---------------- convert f32 -> permuted bf16 hi/lo pairs (R5 layout) -----
__global__ void cvt_split(const float* __restrict__ in, uint32_t* __restrict__ hi,
                          uint32_t* __restrict__ lo, int R, int K)
{
    const int K2 = K >> 1;
    int jj  = blockIdx.x * blockDim.x + threadIdx.x;
    int row = blockIdx.y;
    if (jj >= K2) return;
    int g = jj >> 3, p = jj & 7;
    int jl = (g << 3) + (p >> 1) + ((p & 1) << 2);
    float a0 = 0.f, a1 = 0.f;
    if (row < R) {
        a0 = in[(size_t)row * K + 2 * jl];
        a1 = in[(size_t)row * K + 2 * jl + 1];
    }
    uint32_t h, l;
    split_pack(a0, a1, h, l);
    hi[(size_t)row * K2 + jj] = h;
    lo[(size_t)row * K2 + jj] = l;
}

// ---------------- bf16x3 GEMM (R5 structure; single sync per stage) --------
#define BM 128
#define BN 128
#define BKE 32
#define BUF_U32 (BM * 16)              // 2048
#define STAGE_U32 (4 * BUF_U32)        // 8192
#define GEMM_SMEM_BYTES (3 * STAGE_U32 * 4)   // 98304

__global__ __launch_bounds__(256, 2) void gemm_bf3(
    const uint32_t* __restrict__ Ahi, const uint32_t* __restrict__ Alo,
    const uint32_t* __restrict__ Bhi, const uint32_t* __restrict__ Blo,
    float* __restrict__ C, int M, int N, int K)
{
    extern __shared__ uint32_t dsm[];
    const int K2  = K >> 1;
    const int nst = K / BKE;
    const int tid  = threadIdx.x;
    const int wid  = tid >> 5;
    const int lane = tid & 31;
    const int wm   = wid & 1;
    const int wn   = wid >> 1;
    const int m0   = blockIdx.y * BM;
    const int n0   = blockIdx.x * BN;
    const int lg   = lane >> 2;
    const int lc   = lane & 3;

    const uint32_t sbase = smem_u32p(dsm);
    const int crow = tid >> 1;
    const int cj   = (tid & 1) * 2;
    const int rsw  = (crow >> 1) & 1;

    float acc[4][4][4];
#pragma unroll
    for (int i = 0; i < 4; ++i)
#pragma unroll
        for (int j = 0; j < 4; ++j)
#pragma unroll
            for (int q = 0; q < 4; ++q) acc[i][j][q] = 0.f;

    auto issue = [&](int s) {
        const uint32_t st = sbase + ((s % 3) * STAGE_U32) * 4;
        const size_t ga = (size_t)(m0 + crow) * K2 + (size_t)s * 16;
        const size_t gb = (size_t)(n0 + crow) * K2 + (size_t)s * 16;
#pragma unroll
        for (int c = 0; c < 2; ++c) {
            const int j  = cj + (c ^ rsw);
            const int jp = j ^ (crow & 3);
            const uint32_t d = st + (crow * 16 + jp * 4) * 4;
            cp16(d,                    Ahi + ga + j * 4);
            cp16(d + BUF_U32 * 4,      Alo + ga + j * 4);
            cp16(d + 2 * BUF_U32 * 4,  Bhi + gb + j * 4);
            cp16(d + 3 * BUF_U32 * 4,  Blo + gb + j * 4);
        }
    };

    issue(0); cp_commit();
    issue(1); cp_commit();

    for (int s = 0; s < nst; ++s) {
        if (s < nst - 1) cp_wait1(); else cp_wait0();
        // Single barrier per stage. At this point every thread finished
        // compute(s-1), so issue(s+2) below may safely overwrite the (s-1)
        // buffer ((s+2)%3 == (s-1)%3), and compute(s) reads a different one.
        __syncthreads();
        if (s + 2 < nst) { issue(s + 2); cp_commit(); }

        const uint32_t* st   = dsm + (s % 3) * STAGE_U32;
        const uint32_t* pAhi = st;
        const uint32_t* pAlo = st + BUF_U32;
        const uint32_t* pBhi = st + 2 * BUF_U32;
        const uint32_t* pBlo = st + 3 * BUF_U32;

#pragma unroll
        for (int ks = 0; ks < 2; ++ks) {
            const int jw = ks * 8 + 2 * lc;
            uint2 aH0[4], aH1[4], aL0[4], aL1[4], bH[4], bL[4];
#pragma unroll
            for (int mt = 0; mt < 4; ++mt) {
                int r0 = wm * 64 + mt * 16 + lg;
                int sx = (r0 & 3) << 2;
                int o0 = r0 * 16 + (jw ^ sx);
                int o1 = (r0 + 8) * 16 + (jw ^ sx);
                aH0[mt] = *reinterpret_cast<const uint2*>(pAhi + o0);
                aH1[mt] = *reinterpret_cast<const uint2*>(pAhi + o1);
                aL0[mt] = *reinterpret_cast<const uint2*>(pAlo + o0);
                aL1[mt] = *reinterpret_cast<const uint2*>(pAlo + o1);
            }
#pragma unroll
            for (int nt = 0; nt < 4; ++nt) {
                int rb = wn * 32 + nt * 8 + lg;
                int ob = rb * 16 + (jw ^ ((rb & 3) << 2));
                bH[nt] = *reinterpret_cast<const uint2*>(pBhi + ob);
                bL[nt] = *reinterpret_cast<const uint2*>(pBlo + ob);
            }
#pragma unroll
            for (int mt = 0; mt < 4; ++mt) {
                uint32_t ah[4] = {aH0[mt].x, aH1[mt].x, aH0[mt].y, aH1[mt].y};
#pragma unroll
                for (int nt = 0; nt < 4; ++nt) {
                    uint32_t bh[2] = {bH[nt].x, bH[nt].y};
                    mma_bf16(acc[mt][nt], ah, bh);
                }
            }
#pragma unroll
            for (int mt = 0; mt < 4; ++mt) {
                uint32_t ah[4] = {aH0[mt].x, aH1[mt].x, aH0[mt].y, aH1[mt].y};
#pragma unroll
                for (int nt = 0; nt < 4; ++nt) {
                    uint32_t bl[2] = {bL[nt].x, bL[nt].y};
                    mma_bf16(acc[mt][nt], ah, bl);
                }
            }
#pragma unroll
            for (int mt = 0; mt < 4; ++mt) {
                uint32_t al[4] = {aL0[mt].x, aL1[mt].x, aL0[mt].y, aL1[mt].y};
#pragma unroll
                for (int nt = 0; nt < 4; ++nt) {
                    uint32_t bh[2] = {bH[nt].x, bH[nt].y};
                    mma_bf16(acc[mt][nt], al, bh);
                }
            }
        }
    }

#pragma unroll
    for (int mt = 0; mt < 4; ++mt) {
        int r0 = m0 + wm * 64 + mt * 16 + lg;
#pragma unroll
        for (int nt = 0; nt < 4; ++nt) {
            int gc = n0 + wn * 32 + nt * 8 + lc * 2;
            if (gc < N) {
                *reinterpret_cast<float2*>(&C[(size_t)r0 * N + gc]) =
                    make_float2(acc[mt][nt][0], acc[mt][nt][1]);
                *reinterpret_cast<float2*>(&C[(size_t)(r0 + 8) * N + gc]) =
                    make_float2(acc[mt][nt][2], acc[mt][nt][3]);
            }
        }
    }
}

// ---------------- conv + silu ---------------------------------------------
__global__ void conv_silu_kernel(const float* __restrict__ conv_w,
                                 const float* __restrict__ conv_b)
{
    int idx = blockIdx.x * blockDim.x + threadIdx.x;
    if (idx >= LSEQ * CONV_DIM) return;
    int c = idx % CONV_DIM;
    int t = idx / CONV_DIM;
    const float4 w = *reinterpret_cast<const float4*>(&conv_w[c * 4]);
    const float* col = g_proj + INTER + c;
    float acc = conv_b[c];
    if (t - 3 >= 0) acc = fmaf(col[(size_t)(t - 3) * PROJ], w.x, acc);
    if (t - 2 >= 0) acc = fmaf(col[(size_t)(t - 2) * PROJ], w.y, acc);
    if (t - 1 >= 0) acc = fmaf(col[(size_t)(t - 1) * PROJ], w.z, acc);
    acc = fmaf(col[(size_t)t * PROJ], w.w, acc);
    g_conv[idx] = acc / (1.f + expf(-acc));
}

// ---------------- dt transform ---------------------------------------------
__global__ void dt_kernel(const float* __restrict__ dt_bias,
                          const float* __restrict__ A_log)
{
    int idx = blockIdx.x * blockDim.x + threadIdx.x;
    if (idx >= LSEQ * HEADS) return;
    int h = idx & (HEADS - 1);
    int t = idx >> 6;
    float z = g_proj[(size_t)t * PROJ + INTER + CONV_DIM + h] + dt_bias[h];
    float d = (z > 20.f) ? z : log1pf(expf(z));
    float A = -expf(A_log[h]);
    g_dtv[idx] = d;
    g_dA[idx]  = expf(d * A);
}

// ---------------- selective scan v3 (measured best) --------------------------
#define TCH 8
#define NCH (LSEQ / TCH)
__global__ __launch_bounds__(128) void scan_kernel(const float* __restrict__ D)
{
    const int h   = blockIdx.x >> 2;
    const int ph  = (blockIdx.x >> 1) & 1;
    const int nh  = blockIdx.x & 1;
    const int tid = threadIdx.x;
    const int pl  = tid >> 2;
    const int q   = tid & 3;
    const int n0  = q * 8;
    const float Dh = D[h];
    float* yout = nh ? g_y2 : g_y;

    __shared__ float sB[2][TCH][32], sC[2][TCH][32], sX[2][TCH][32];
    __shared__ float sDT[2][TCH], sDA[2][TCH];

    const int tl   = tid >> 4;
    const int col2 = tid & 15;

    {
        const float* rowp = g_conv + (size_t)tl * CONV_DIM;
        *reinterpret_cast<float2*>(&sB[0][tl][col2 * 2]) =
            *reinterpret_cast<const float2*>(&rowp[INTER + nh * 32 + col2 * 2]);
        *reinterpret_cast<float2*>(&sC[0][tl][col2 * 2]) =
            *reinterpret_cast<const float2*>(&rowp[INTER + STATE + nh * 32 + col2 * 2]);
        *reinterpret_cast<float2*>(&sX[0][tl][col2 * 2]) =
            *reinterpret_cast<const float2*>(&rowp[h * HEAD_DIM + ph * 32 + col2 * 2]);
        if (tid < TCH)           sDT[0][tid]       = g_dtv[tid * HEADS + h];
        else if (tid < 2 * TCH)  sDA[0][tid - TCH] = g_dA[(tid - TCH) * HEADS + h];
    }
    __syncthreads();

    float s[8];
#pragma unroll
    for (int i = 0; i < 8; ++i) s[i] = 0.f;

    for (int c = 0; c < NCH; ++c) {
        const int buf = c & 1;
        const int t0  = c * TCH;
        const bool more = (c + 1 < NCH);

        float2 nB, nC, nX; float nS = 0.f;
        if (more) {
            const float* rowp = g_conv + (size_t)(t0 + TCH + tl) * CONV_DIM;
            nB = *reinterpret_cast<const float2*>(&rowp[INTER + nh * 32 + col2 * 2]);
            nC = *reinterpret_cast<const float2*>(&rowp[INTER + STATE + nh * 32 + col2 * 2]);
            nX = *reinterpret_cast<const float2*>(&rowp[h * HEAD_DIM + ph * 32 + col2 * 2]);
            if (tid < TCH)           nS = g_dtv[(t0 + TCH + tid) * HEADS + h];
            else if (tid < 2 * TCH)  nS = g_dA[(t0 + TCH + tid - TCH) * HEADS + h];
        }

#pragma unroll
        for (int k = 0; k < TCH; ++k) {
            const float a   = sDA[buf][k];
            const float dtv = sDT[buf][k];
            const float xv  = sX[buf][k][pl];
            const float dtx = dtv * xv;
            float4 b0 = *reinterpret_cast<const float4*>(&sB[buf][k][n0]);
            float4 b1 = *reinterpret_cast<const float4*>(&sB[buf][k][n0 + 4]);
            float4 c0 = *reinterpret_cast<const float4*>(&sC[buf][k][n0]);
            float4 c1 = *reinterpret_cast<const float4*>(&sC[buf][k][n0 + 4]);
            s[0] = fmaf(a, s[0], dtx * b0.x);
            s[1] = fmaf(a, s[1], dtx * b0.y);
            s[2] = fmaf(a, s[2], dtx * b0.z);
            s[3] = fmaf(a, s[3], dtx * b0.w);
            s[4] = fmaf(a, s[4], dtx * b1.x);
            s[5] = fmaf(a, s[5], dtx * b1.y);
            s[6] = fmaf(a, s[6], dtx * b1.z);
            s[7] = fmaf(a, s[7], dtx * b1.w);
            float e0 = fmaf(s[1], c0.y, s[0] * c0.x);
            float e1 = fmaf(s[3], c0.w, s[2] * c0.z);
            float e2 = fmaf(s[5], c1.y, s[4] * c1.x);
            float e3 = fmaf(s[7], c1.w, s[6] * c1.z);
            float accv = (e0 + e1) + (e2 + e3);
            accv += __shfl_xor_sync(0xffffffffu, accv, 1);
            accv += __shfl_xor_sync(0xffffffffu, accv, 2);
            if (q == 0) {
                float o = accv + (nh == 0 ? Dh * xv : 0.f);
                yout[(size_t)(t0 + k) * INTER + h * HEAD_DIM + ph * 32 + pl] = o;
            }
        }

        if (more) {
            const int nb = buf ^ 1;
            *reinterpret_cast<float2*>(&sB[nb][tl][col2 * 2]) = nB;
            *reinterpret_cast<float2*>(&sC[nb][tl][col2 * 2]) = nC;
            *reinterpret_cast<float2*>(&sX[nb][tl][col2 * 2]) = nX;
            if (tid < TCH)           sDT[nb][tid]       = nS;
            else if (tid < 2 * TCH)  sDA[nb][tid - TCH] = nS;
        }
        __syncthreads();
    }
}

// ---------------- RMSNorm * silu(gate) -> bf16 hi/lo (R5 permutation) ---------
__global__ __launch_bounds__(256) void norm_gate_cvt(const float* __restrict__ nw)
{
    const int t = blockIdx.x;
    const float* y1 = g_y  + (size_t)t * INTER;
    const float* y2 = g_y2 + (size_t)t * INTER;
    const float* gp = g_proj + (size_t)t * PROJ;
    __shared__ float red[256];
    float ss = 0.f;
    for (int c = threadIdx.x; c < INTER; c += 256) {
        float v = y1[c] + y2[c];
        ss = fmaf(v, v, ss);
    }
    red[threadIdx.x] = ss;
    __syncthreads();
    for (int off = 128; off > 0; off >>= 1) {
        if (threadIdx.x < off) red[threadIdx.x] += red[threadIdx.x + off];
        __syncthreads();
    }
    const float r = rsqrtf(red[0] / (float)INTER + 1e-6f);

    const int K2 = INTER / 2;
    for (int J = threadIdx.x; J < K2; J += 256) {
        int g = J >> 3, p = J & 7;
        int jl = (g << 3) + (p >> 1) + ((p & 1) << 2);
        int c0 = 2 * jl;
        float ga = gp[c0], gb = gp[c0 + 1];
        float v0 = (y1[c0] + y2[c0]) * r * nw[c0] * (ga / (1.f + expf(-ga)));
        float v1 = (y1[c0 + 1] + y2[c0 + 1]) * r * nw[c0 + 1] * (gb / (1.f + expf(-gb)));
        uint32_t h, l;
        split_pack(v0, v1, h, l);
        g_yn_hi[(size_t)t * K2 + J] = h;
        g_yn_lo[(size_t)t * K2 + J] = l;
    }
}

// ---------------- launch ------------------------------------------------------
extern "C" void kernel_launch(void* const* d_in, const int* in_sizes, int n_in,
                              void* d_out, int out_size)
{
    const float* hidden     = (const float*)d_in[0];
    const float* in_proj_w  = (const float*)d_in[1];
    const float* conv_w     = (const float*)d_in[2];
    const float* conv_b     = (const float*)d_in[3];
    const float* dt_bias    = (const float*)d_in[4];
    const float* A_log      = (const float*)d_in[5];
    const float* Dv         = (const float*)d_in[6];
    const float* norm_w     = (const float*)d_in[7];
    const float* out_proj_w = (const float*)d_in[8];
    float* out = (float*)d_out;

    float* p_proj = nullptr;
    cudaGetSymbolAddress((void**)&p_proj, g_proj);
    uint32_t *p_hhi, *p_hlo, *p_w1hi, *p_w1lo, *p_w2hi, *p_w2lo, *p_ynhi, *p_ynlo;
    cudaGetSymbolAddress((void**)&p_hhi, g_h_hi);
    cudaGetSymbolAddress((void**)&p_hlo, g_h_lo);
    cudaGetSymbolAddress((void**)&p_w1hi, g_w1_hi);
    cudaGetSymbolAddress((void**)&p_w1lo, g_w1_lo);
    cudaGetSymbolAddress((void**)&p_w2hi, g_w2_hi);
    cudaGetSymbolAddress((void**)&p_w2lo, g_w2_lo);
    cudaGetSymbolAddress((void**)&p_ynhi, g_yn_hi);
    cudaGetSymbolAddress((void**)&p_ynlo, g_yn_lo);

    cudaFuncSetAttribute(gemm_bf3, cudaFuncAttributeMaxDynamicSharedMemorySize, GEMM_SMEM_BYTES);

    cvt_split<<<dim3(HIDDEN / 2 / 256, LSEQ), 256>>>(hidden, p_hhi, p_hlo, LSEQ, HIDDEN);
    cvt_split<<<dim3(HIDDEN / 2 / 256, W1_RPAD), 256>>>(in_proj_w, p_w1hi, p_w1lo, PROJ, HIDDEN);
    cvt_split<<<dim3(INTER / 2 / 256, HIDDEN), 256>>>(out_proj_w, p_w2hi, p_w2lo, HIDDEN, INTER);

    // GEMM1: proj = hidden @ in_proj_w^T : M=2048, N=8384 (pad 8448), K=2048
    gemm_bf3<<<dim3(W1_RPAD / BN, LSEQ / BM), 256, GEMM_SMEM_BYTES>>>(
        p_hhi, p_hlo, p_w1hi, p_w1lo, p_proj, LSEQ, PROJ, HIDDEN);

    {
        int total = LSEQ * CONV_DIM;
        conv_silu_kernel<<<(total + 255) / 256, 256>>>(conv_w, conv_b);
    }
    {
        int total = LSEQ * HEADS;
        dt_kernel<<<(total + 255) / 256, 256>>>(dt_bias, A_log);
    }
    scan_kernel<<<HEADS * 4, 128>>>(Dv);
    norm_gate_cvt<<<LSEQ, 256>>>(norm_w);

    // GEMM2: out = y' @ out_proj_w^T : M=2048, N=2048, K=4096
    gemm_bf3<<<dim3(HIDDEN / BN, LSEQ / BM), 256, GEMM_SMEM_BYTES>>>(
        p_ynhi, p_ynlo, p_w2hi, p_w2lo, out, LSEQ, HIDDEN, INTER);
}